// round 16
// baseline (speedup 1.0000x reference)
#include <cuda_runtime.h>
#include <cuda_bf16.h>
#include <cuda_fp16.h>
#include <math.h>
#include <stdint.h>

// ---------------------------------------------------------------------------
// Problem constants
// ---------------------------------------------------------------------------
#define BATCH     2
#define NQ        10000
#define MTOT      21760
#define EMBED     256
#define HEADS     8
#define HEAD_DIM  32
#define LEVELS    4
#define POINTS    4
#define COMBOS    (HEADS*LEVELS*POINTS)
#define KDIM      256
#define NQC       384            // combined off(256) + attn(128) width

#define MV (BATCH * MTOT)        // 43520
#define MQ (BATCH * NQ)          // 20000
#define GRID_V 680               // 2 x 340
#define GRID_Q 471               // 3 x 157

__device__ __constant__ int c_shape[LEVELS]  = {128, 64, 32, 16};
__device__ __constant__ int c_start[LEVELS]  = {0, 16384, 20480, 21504};

// ---------------------------------------------------------------------------
// Device scratch
// ---------------------------------------------------------------------------
__device__ __half g_vh[BATCH * MTOT * EMBED];          // projected value, fp16
__device__ float  g_qc[BATCH * NQ * NQC];              // [off(256) | attn(128)]

__device__ __nv_bfloat16 g_val_hi[MV * KDIM], g_val_lo[MV * KDIM];
__device__ __nv_bfloat16 g_q_hi[MQ * KDIM],   g_q_lo[MQ * KDIM];
__device__ __nv_bfloat16 g_wv_hi[256 * KDIM], g_wv_lo[256 * KDIM];
__device__ __nv_bfloat16 g_wq_hi[NQC * KDIM], g_wq_lo[NQC * KDIM];
__device__ float g_bq[NQC];

// ---------------------------------------------------------------------------
// PTX wrappers
// ---------------------------------------------------------------------------
__device__ __forceinline__ uint32_t smem_u32(const void* p) {
    uint32_t a;
    asm("{ .reg .u64 t; cvta.to.shared.u64 t, %1; cvt.u32.u64 %0, t; }" : "=r"(a) : "l"(p));
    return a;
}
__device__ __forceinline__ void ldsm4(uint32_t* r, uint32_t addr) {
    asm volatile("ldmatrix.sync.aligned.m8n8.x4.shared.b16 {%0,%1,%2,%3}, [%4];"
        : "=r"(r[0]), "=r"(r[1]), "=r"(r[2]), "=r"(r[3]) : "r"(addr));
}
__device__ __forceinline__ void mma_bf16(float* c, const uint32_t* a, const uint32_t* b) {
    asm volatile("mma.sync.aligned.m16n8k16.row.col.f32.bf16.bf16.f32 "
        "{%0,%1,%2,%3}, {%4,%5,%6,%7}, {%8,%9}, {%0,%1,%2,%3};"
        : "+f"(c[0]), "+f"(c[1]), "+f"(c[2]), "+f"(c[3])
        : "r"(a[0]), "r"(a[1]), "r"(a[2]), "r"(a[3]), "r"(b[0]), "r"(b[1]));
}
__device__ __forceinline__ void cpa16(uint32_t dst, const void* src, uint32_t sz) {
    asm volatile("cp.async.ca.shared.global [%0], [%1], 16, %2;" :: "r"(dst), "l"(src), "r"(sz));
}
#define CPA_COMMIT()  asm volatile("cp.async.commit_group;" ::: "memory")
#define CPA_WAIT(n)   asm volatile("cp.async.wait_group %0;" :: "n"(n) : "memory")

// ---------------------------------------------------------------------------
// Prep: activation splits + weight transposes + bias concat (one launch)
// ---------------------------------------------------------------------------
__device__ __forceinline__ void split4(const float* in, __nv_bfloat16* hi,
                                       __nv_bfloat16* lo, int i) {
    float4 a = ((const float4*)in)[i];
    __nv_bfloat16 h[4], l[4];
    float v[4] = {a.x, a.y, a.z, a.w};
#pragma unroll
    for (int j = 0; j < 4; j++) {
        h[j] = __float2bfloat16(v[j]);
        l[j] = __float2bfloat16(v[j] - __bfloat162float(h[j]));
    }
    ((uint2*)hi)[i] = *(uint2*)h;
    ((uint2*)lo)[i] = *(uint2*)l;
}

#define NV4 (MV * KDIM / 4)
#define NQ4 (MQ * KDIM / 4)
#define NWV (256 * KDIM)
#define NWQ (NQC * KDIM)
#define PREP_TOT (NV4 + NQ4 + NWV + NWQ + NQC)

__global__ void prep_all(const float* __restrict__ value, const float* __restrict__ query,
                         const float* __restrict__ Wv, const float* __restrict__ Wo,
                         const float* __restrict__ Wa,
                         const float* __restrict__ b_off, const float* __restrict__ b_attn)
{
    int i = blockIdx.x * blockDim.x + threadIdx.x;
    if (i < NV4) { split4(value, g_val_hi, g_val_lo, i); return; }
    i -= NV4;
    if (i < NQ4) { split4(query, g_q_hi, g_q_lo, i); return; }
    i -= NQ4;
    if (i < NWV) {
        int n = i >> 8, k = i & 255;
        float v = Wv[k * 256 + n];
        __nv_bfloat16 h = __float2bfloat16(v);
        g_wv_hi[i] = h;
        g_wv_lo[i] = __float2bfloat16(v - __bfloat162float(h));
        return;
    }
    i -= NWV;
    if (i < NWQ) {
        int n = i >> 8, k = i & 255;
        float v = (n < 256) ? Wo[k * 256 + n] : Wa[k * 128 + (n - 256)];
        __nv_bfloat16 h = __float2bfloat16(v);
        g_wq_hi[i] = h;
        g_wq_lo[i] = __float2bfloat16(v - __bfloat162float(h));
        return;
    }
    i -= NWQ;
    if (i < NQC) g_bq[i] = (i < 256) ? b_off[i] : b_attn[i - 256];
}

// ---------------------------------------------------------------------------
// Fused HMMA GEMM: tile 128x128, BK=64, 512 thr / 16 warps (4m x 4n),
// NOW 3-stage cp.async ring (two chunk-loads in flight).
// ---------------------------------------------------------------------------
#define OAL   16384
#define OBH   32768
#define OBL   49152
#define STG   65536
#define SM_TOTAL (3*STG)         // 192 KB

__device__ __forceinline__ uint32_t sw128(int row, int ch) {
    return (uint32_t)row * 128u + (uint32_t)((ch ^ (row & 7)) << 4);
}

__global__ __launch_bounds__(512) void gemm_fused(const float* __restrict__ b_v)
{
    extern __shared__ char smem[];
    const uint32_t sb = smem_u32(smem);
    const int tid  = threadIdx.x;
    const int wid  = tid >> 5;
    const int lane = tid & 31;
    const int wm   = wid & 3;        // 4 m-groups of 32 rows
    const int wn   = wid >> 2;       // 4 n-groups of 32 cols

    const __nv_bfloat16 *Ahi, *Alo, *Bh, *Bl;
    const float* bias;
    __half* Ch = nullptr;
    float*  Cf = nullptr;
    int M, N, cx, cy;
    if (blockIdx.x < GRID_V) {
        cx = blockIdx.x & 1;  cy = blockIdx.x >> 1;
        Ahi = g_val_hi; Alo = g_val_lo; Bh = g_wv_hi; Bl = g_wv_lo;
        bias = b_v; Ch = g_vh; M = MV; N = 256;
    } else {
        int b2 = blockIdx.x - GRID_V;
        cx = b2 % 3;  cy = b2 / 3;
        Ahi = g_q_hi; Alo = g_q_lo; Bh = g_wq_hi; Bl = g_wq_lo;
        bias = g_bq; Cf = g_qc; M = MQ; N = NQC;
    }
    const int row0 = cy * 128;
    const int col0 = cx * 128;

    float acc[2][4][4];
#pragma unroll
    for (int a = 0; a < 2; a++)
#pragma unroll
        for (int b = 0; b < 4; b++)
#pragma unroll
            for (int f = 0; f < 4; f++) acc[a][b][f] = 0.f;

#define LOAD_STAGE(stbase, k0)                                                  \
    do {                                                                        \
        _Pragma("unroll")                                                       \
        for (int i = 0; i < 2; i++) {                                           \
            int c   = tid + i * 512;       /* 0..1023 */                        \
            int row = c >> 3;                                                   \
            int ch  = c & 7;                                                    \
            uint32_t sw = sw128(row, ch);                                       \
            int gr = row0 + row;                                                \
            uint32_t sz = (gr < M) ? 16u : 0u;                                  \
            size_t ga = (size_t)(gr < M ? gr : 0) * KDIM + (k0) + ch * 8;       \
            cpa16(sb + (stbase) + sw,        Ahi + ga, sz);                     \
            cpa16(sb + (stbase) + OAL + sw,  Alo + ga, sz);                     \
            size_t gb = (size_t)(col0 + row) * KDIM + (k0) + ch * 8;            \
            cpa16(sb + (stbase) + OBH + sw,  Bh + gb, 16u);                     \
            cpa16(sb + (stbase) + OBL + sw,  Bl + gb, 16u);                     \
        }                                                                       \
    } while (0)

    // prologue: stages 0,1 in flight
    LOAD_STAGE(0, 0);
    CPA_COMMIT();
    LOAD_STAGE(STG, 64);
    CPA_COMMIT();

#pragma unroll
    for (int cc = 0; cc < 4; cc++) {
        const uint32_t st = (uint32_t)(cc % 3) * STG;
        if (cc < 2) {
            LOAD_STAGE((uint32_t)((cc + 2) % 3) * STG, (cc + 2) * 64);
            CPA_COMMIT();
            CPA_WAIT(2);
        } else if (cc == 2) {
            CPA_WAIT(1);
        } else {
            CPA_WAIT(0);
        }
        __syncthreads();

#pragma unroll
        for (int ks = 0; ks < 4; ks++) {
            uint32_t ah[2][4], al[2][4];
#pragma unroll
            for (int tm = 0; tm < 2; tm++) {
                int rA = wm * 32 + tm * 16 + (lane & 15);
                int ch = 2 * ks + (lane >> 4);
                uint32_t ad = sb + st + sw128(rA, ch);
                ldsm4(ah[tm], ad);
                ldsm4(al[tm], ad + OAL);
            }
#pragma unroll
            for (int g = 0; g < 2; g++) {
                int rB  = wn * 32 + g * 16 + ((lane >> 4) & 1) * 8 + (lane & 7);
                int chb = 2 * ks + ((lane >> 3) & 1);
                uint32_t bd = sb + st + OBH + sw128(rB, chb);
                uint32_t bh[4], bl[4];
                ldsm4(bh, bd);
                ldsm4(bl, bd + (OBL - OBH));
#pragma unroll
                for (int tm = 0; tm < 2; tm++) {
                    mma_bf16(acc[tm][2*g],   ah[tm], bh);
                    mma_bf16(acc[tm][2*g],   ah[tm], bl);
                    mma_bf16(acc[tm][2*g],   al[tm], bh);
                    mma_bf16(acc[tm][2*g+1], ah[tm], bh + 2);
                    mma_bf16(acc[tm][2*g+1], ah[tm], bl + 2);
                    mma_bf16(acc[tm][2*g+1], al[tm], bh + 2);
                }
            }
        }
        __syncthreads();
    }

    // ---- epilogue ----
    const int row_in = lane >> 2;
    const int col_in = 2 * (lane & 3);
#pragma unroll
    for (int tm = 0; tm < 2; tm++) {
        const int gr0 = row0 + wm * 32 + tm * 16 + row_in;
#pragma unroll
        for (int j = 0; j < 4; j++) {
            const int gcol = col0 + wn * 32 + j * 8 + col_in;
            const float bx = bias[gcol];
            const float by = bias[gcol + 1];
            if (Ch) {
                if (gr0 < M)
                    *(__half2*)&Ch[(size_t)gr0 * N + gcol] =
                        __floats2half2_rn(acc[tm][j][0] + bx, acc[tm][j][1] + by);
                if (gr0 + 8 < M)
                    *(__half2*)&Ch[(size_t)(gr0 + 8) * N + gcol] =
                        __floats2half2_rn(acc[tm][j][2] + bx, acc[tm][j][3] + by);
            } else {
                if (gr0 < M)
                    *(float2*)&Cf[(size_t)gr0 * N + gcol] =
                        make_float2(acc[tm][j][0] + bx, acc[tm][j][1] + by);
                if (gr0 + 8 < M)
                    *(float2*)&Cf[(size_t)(gr0 + 8) * N + gcol] =
                        make_float2(acc[tm][j][2] + bx, acc[tm][j][3] + by);
            }
        }
    }
#undef LOAD_STAGE
}

// ---------------------------------------------------------------------------
// Sampler: R14 verbatim (LDG.128, 4 lanes/corner, butterfly reduce)
// ---------------------------------------------------------------------------
#define QPB 2

__global__ __launch_bounds__(256) void deform_sample(
    const float* __restrict__ ref_points, float* __restrict__ out)
{
    __shared__ float4 s_w[QPB * COMBOS];
    __shared__ int4   s_i[QPB * COMBOS];

    const int t = threadIdx.x;

    // ---------------- Phase 1 ----------------
    {
        const int q    = t >> 7;
        const int c    = t & 127;
        const int head = c >> 4;
        const int i16  = c & 15;
        const int lv   = i16 >> 2;
        const int bn   = blockIdx.x * QPB + q;
        const int b    = bn / NQ;

        float lg = g_qc[(size_t)bn * NQC + 256 + c];
        float mx = lg;
#pragma unroll
        for (int s = 8; s >= 1; s >>= 1)
            mx = fmaxf(mx, __shfl_xor_sync(0xffffffffu, mx, s));
        float e = __expf(lg - mx);
        float ssum = e;
#pragma unroll
        for (int s = 8; s >= 1; s >>= 1)
            ssum += __shfl_xor_sync(0xffffffffu, ssum, s);
        const float aw = e / ssum;

        const float2 od = *(const float2*)&g_qc[(size_t)bn * NQC + 2 * c];
        const float rx = ref_points[bn * 2 + 0];
        const float ry = ref_points[bn * 2 + 1];

        const int   S  = c_shape[lv];
        const float fS = (float)S;
        const float x = (rx + od.x / fS) * fS - 0.5f;
        const float y = (ry + od.y / fS) * fS - 0.5f;
        const float x0f = floorf(x), y0f = floorf(y);
        const float lx = x - x0f, ly = y - y0f;
        const int x0 = (int)x0f, y0 = (int)y0f;
        const int x1 = x0 + 1,   y1 = y0 + 1;

        const bool vx0 = ((unsigned)x0 < (unsigned)S);
        const bool vx1 = ((unsigned)x1 < (unsigned)S);
        const bool vy0 = ((unsigned)y0 < (unsigned)S);
        const bool vy1 = ((unsigned)y1 < (unsigned)S);

        const int xc0 = min(max(x0, 0), S - 1);
        const int xc1 = min(max(x1, 0), S - 1);
        const int yc0 = min(max(y0, 0), S - 1);
        const int yc1 = min(max(y1, 0), S - 1);

        float4 wv;
        wv.x = (vx0 && vy0) ? (1.f - lx) * (1.f - ly) * aw : 0.f;
        wv.y = (vx1 && vy0) ? lx * (1.f - ly) * aw : 0.f;
        wv.z = (vx0 && vy1) ? (1.f - lx) * ly * aw : 0.f;
        wv.w = (vx1 && vy1) ? lx * ly * aw : 0.f;

        const int base = b * MTOT + c_start[lv];
        const int hoff = head * HEAD_DIM;
        int4 iv;
        iv.x = (base + yc0 * S + xc0) * EMBED + hoff;
        iv.y = (base + yc0 * S + xc1) * EMBED + hoff;
        iv.z = (base + yc1 * S + xc0) * EMBED + hoff;
        iv.w = (base + yc1 * S + xc1) * EMBED + hoff;

        s_w[t] = wv;
        s_i[t] = iv;
    }
    __syncthreads();

    // ---------------- Phase 2 ----------------
    const int head  = t >> 5;
    const int lane  = t & 31;
    const int cslot = lane >> 2;
    const int sub   = cslot >> 2;
    const int corner= cslot & 3;
    const int choff = (lane & 3) * 8;

    const int*   si  = (const int*)s_i;
    const float* swf = (const float*)s_w;

#pragma unroll
    for (int q = 0; q < QPB; q++) {
        const int bn   = blockIdx.x * QPB + q;
        const int slot = q * COMBOS + head * (LEVELS * POINTS);

        float acc[8];
#pragma unroll
        for (int j = 0; j < 8; j++) acc[j] = 0.f;

#pragma unroll
        for (int i = 0; i < 8; i++) {
            const int e   = (slot + 2 * i + sub) * 4 + corner;
            const int idx = si[e];
            const float w = swf[e];
            const uint4 d = __ldg((const uint4*)&g_vh[idx + choff]);
            const __half2* h2 = (const __half2*)&d;
#pragma unroll
            for (int j = 0; j < 4; j++) {
                float2 f = __half22float2(h2[j]);
                acc[2*j]   = fmaf(w, f.x, acc[2*j]);
                acc[2*j+1] = fmaf(w, f.y, acc[2*j+1]);
            }
        }

#pragma unroll
        for (int s = 4; s <= 16; s <<= 1)
#pragma unroll
            for (int j = 0; j < 8; j++)
                acc[j] += __shfl_xor_sync(0xffffffffu, acc[j], s);

        if (lane < 4) {
            float* op = out + (size_t)bn * EMBED + head * HEAD_DIM + choff;
            *(float4*)op       = make_float4(acc[0], acc[1], acc[2], acc[3]);
            *(float4*)(op + 4) = make_float4(acc[4], acc[5], acc[6], acc[7]);
        }
    }
}

// ---------------------------------------------------------------------------
// Launch: 3 kernels total
// ---------------------------------------------------------------------------
extern "C" void kernel_launch(void* const* d_in, const int* in_sizes, int n_in,
                              void* d_out, int out_size)
{
    const float* query  = (const float*)d_in[0];
    const float* value  = (const float*)d_in[2];
    const float* refpts = (const float*)d_in[3];
    const float* W_off  = (const float*)d_in[6];
    const float* b_off  = (const float*)d_in[7];
    const float* W_attn = (const float*)d_in[8];
    const float* b_attn = (const float*)d_in[9];
    const float* W_v    = (const float*)d_in[10];
    const float* b_v    = (const float*)d_in[11];
    float* out = (float*)d_out;

    cudaFuncSetAttribute(gemm_fused, cudaFuncAttributeMaxDynamicSharedMemorySize, SM_TOTAL);

    prep_all<<<(PREP_TOT + 255) / 256, 256>>>(value, query, W_v, W_off, W_attn,
                                              b_off, b_attn);

    gemm_fused<<<GRID_V + GRID_Q, 512, SM_TOTAL>>>(b_v);

    deform_sample<<<(BATCH * NQ) / QPB, 256>>>(refpts, out);
}

// round 17
// speedup vs baseline: 1.1686x; 1.1686x over previous
#include <cuda_runtime.h>
#include <cuda_bf16.h>
#include <cuda_fp16.h>
#include <math.h>
#include <stdint.h>

// ---------------------------------------------------------------------------
// Problem constants
// ---------------------------------------------------------------------------
#define BATCH     2
#define NQ        10000
#define MTOT      21760
#define EMBED     256
#define HEADS     8
#define HEAD_DIM  32
#define LEVELS    4
#define POINTS    4
#define COMBOS    (HEADS*LEVELS*POINTS)
#define KDIM      256
#define NQC       384            // combined off(256) + attn(128) width

#define MV (BATCH * MTOT)        // 43520
#define MQ (BATCH * NQ)          // 20000
#define GRID_V 680               // 2 x 340
#define GRID_Q 471               // 3 x 157

__device__ __constant__ int c_shape[LEVELS]  = {128, 64, 32, 16};
__device__ __constant__ int c_start[LEVELS]  = {0, 16384, 20480, 21504};

// ---------------------------------------------------------------------------
// Device scratch
// ---------------------------------------------------------------------------
__device__ __half g_vh[BATCH * MTOT * EMBED];          // projected value, fp16
__device__ float  g_qc[BATCH * NQ * NQC];              // [off(256) | attn(128)]

__device__ __half g_val_h[MV * KDIM];                  // A: fp16 single
__device__ __half g_q_h[MQ * KDIM];
__device__ __half g_wv_hi[256 * KDIM], g_wv_lo[256 * KDIM];   // W: fp16 hi/lo
__device__ __half g_wq_hi[NQC * KDIM], g_wq_lo[NQC * KDIM];
__device__ float g_bq[NQC];

// ---------------------------------------------------------------------------
// PTX wrappers
// ---------------------------------------------------------------------------
__device__ __forceinline__ uint32_t smem_u32(const void* p) {
    uint32_t a;
    asm("{ .reg .u64 t; cvta.to.shared.u64 t, %1; cvt.u32.u64 %0, t; }" : "=r"(a) : "l"(p));
    return a;
}
__device__ __forceinline__ void ldsm4(uint32_t* r, uint32_t addr) {
    asm volatile("ldmatrix.sync.aligned.m8n8.x4.shared.b16 {%0,%1,%2,%3}, [%4];"
        : "=r"(r[0]), "=r"(r[1]), "=r"(r[2]), "=r"(r[3]) : "r"(addr));
}
__device__ __forceinline__ void mma_f16(float* c, const uint32_t* a, const uint32_t* b) {
    asm volatile("mma.sync.aligned.m16n8k16.row.col.f32.f16.f16.f32 "
        "{%0,%1,%2,%3}, {%4,%5,%6,%7}, {%8,%9}, {%0,%1,%2,%3};"
        : "+f"(c[0]), "+f"(c[1]), "+f"(c[2]), "+f"(c[3])
        : "r"(a[0]), "r"(a[1]), "r"(a[2]), "r"(a[3]), "r"(b[0]), "r"(b[1]));
}
__device__ __forceinline__ void cpa16(uint32_t dst, const void* src, uint32_t sz) {
    asm volatile("cp.async.ca.shared.global [%0], [%1], 16, %2;" :: "r"(dst), "l"(src), "r"(sz));
}
#define CPA_COMMIT()  asm volatile("cp.async.commit_group;" ::: "memory")
#define CPA_WAIT1()   asm volatile("cp.async.wait_group 1;" ::: "memory")
#define CPA_WAIT0()   asm volatile("cp.async.wait_group 0;" ::: "memory")

// ---------------------------------------------------------------------------
// Prep: fp16 activation convert + fp16 hi/lo weight transpose + bias concat
// ---------------------------------------------------------------------------
__device__ __forceinline__ void cvt4(const float* in, __half* dst, int i) {
    float4 a = ((const float4*)in)[i];
    __half h[4];
    h[0] = __float2half_rn(a.x);
    h[1] = __float2half_rn(a.y);
    h[2] = __float2half_rn(a.z);
    h[3] = __float2half_rn(a.w);
    ((uint2*)dst)[i] = *(uint2*)h;
}

#define NV4 (MV * KDIM / 4)
#define NQ4 (MQ * KDIM / 4)
#define NWV (256 * KDIM)
#define NWQ (NQC * KDIM)
#define PREP_TOT (NV4 + NQ4 + NWV + NWQ + NQC)

__global__ void prep_all(const float* __restrict__ value, const float* __restrict__ query,
                         const float* __restrict__ Wv, const float* __restrict__ Wo,
                         const float* __restrict__ Wa,
                         const float* __restrict__ b_off, const float* __restrict__ b_attn)
{
    int i = blockIdx.x * blockDim.x + threadIdx.x;
    if (i < NV4) { cvt4(value, g_val_h, i); return; }
    i -= NV4;
    if (i < NQ4) { cvt4(query, g_q_h, i); return; }
    i -= NQ4;
    if (i < NWV) {
        int n = i >> 8, k = i & 255;
        float v = Wv[k * 256 + n];
        __half h = __float2half_rn(v);
        g_wv_hi[i] = h;
        g_wv_lo[i] = __float2half_rn(v - __half2float(h));
        return;
    }
    i -= NWV;
    if (i < NWQ) {
        int n = i >> 8, k = i & 255;
        float v = (n < 256) ? Wo[k * 256 + n] : Wa[k * 128 + (n - 256)];
        __half h = __float2half_rn(v);
        g_wq_hi[i] = h;
        g_wq_lo[i] = __float2half_rn(v - __half2float(h));
        return;
    }
    i -= NWQ;
    if (i < NQC) g_bq[i] = (i < 256) ? b_off[i] : b_attn[i - 256];
}

// ---------------------------------------------------------------------------
// Fused HMMA GEMM: C = A_f16 * (Wh + Wl)^T + bias.   2-term fp16.
// Tile 128x128, BK=64, 2-stage cp.async, 512 thr / 16 warps (4m x 4n).
// Stage (48KB): [A 16K][B_hi 16K][B_lo 16K]
// ---------------------------------------------------------------------------
#define OBH   16384
#define OBL   32768
#define STG   49152
#define SM_TOTAL (2*STG)         // 96 KB

__device__ __forceinline__ uint32_t sw128(int row, int ch) {
    return (uint32_t)row * 128u + (uint32_t)((ch ^ (row & 7)) << 4);
}

__global__ __launch_bounds__(512) void gemm_fused(const float* __restrict__ b_v)
{
    extern __shared__ char smem[];
    const uint32_t sb = smem_u32(smem);
    const int tid  = threadIdx.x;
    const int wid  = tid >> 5;
    const int lane = tid & 31;
    const int wm   = wid & 3;        // 4 m-groups of 32 rows
    const int wn   = wid >> 2;       // 4 n-groups of 32 cols

    const __half *Af, *Bh, *Bl;
    const float* bias;
    __half* Ch = nullptr;
    float*  Cf = nullptr;
    int M, N, cx, cy;
    if (blockIdx.x < GRID_V) {
        cx = blockIdx.x & 1;  cy = blockIdx.x >> 1;
        Af = g_val_h; Bh = g_wv_hi; Bl = g_wv_lo;
        bias = b_v; Ch = g_vh; M = MV; N = 256;
    } else {
        int b2 = blockIdx.x - GRID_V;
        cx = b2 % 3;  cy = b2 / 3;
        Af = g_q_h; Bh = g_wq_hi; Bl = g_wq_lo;
        bias = g_bq; Cf = g_qc; M = MQ; N = NQC;
    }
    const int row0 = cy * 128;
    const int col0 = cx * 128;

    float acc[2][4][4];
#pragma unroll
    for (int a = 0; a < 2; a++)
#pragma unroll
        for (int b = 0; b < 4; b++)
#pragma unroll
            for (int f = 0; f < 4; f++) acc[a][b][f] = 0.f;

#define LOAD_STAGE(stbase, k0)                                                  \
    do {                                                                        \
        _Pragma("unroll")                                                       \
        for (int i = 0; i < 2; i++) {                                           \
            int c   = tid + i * 512;       /* 0..1023 */                        \
            int row = c >> 3;                                                   \
            int ch  = c & 7;                                                    \
            uint32_t sw = sw128(row, ch);                                       \
            int gr = row0 + row;                                                \
            uint32_t sz = (gr < M) ? 16u : 0u;                                  \
            size_t ga = (size_t)(gr < M ? gr : 0) * KDIM + (k0) + ch * 8;       \
            cpa16(sb + (stbase) + sw, Af + ga, sz);                             \
            size_t gb = (size_t)(col0 + row) * KDIM + (k0) + ch * 8;            \
            cpa16(sb + (stbase) + OBH + sw, Bh + gb, 16u);                      \
            cpa16(sb + (stbase) + OBL + sw, Bl + gb, 16u);                      \
        }                                                                       \
    } while (0)

    LOAD_STAGE(0, 0);
    CPA_COMMIT();

#pragma unroll
    for (int cc = 0; cc < 4; cc++) {
        const uint32_t st = (uint32_t)(cc & 1) * STG;
        if (cc < 3) {
            LOAD_STAGE((uint32_t)((cc + 1) & 1) * STG, (cc + 1) * 64);
            CPA_COMMIT();
            CPA_WAIT1();
        } else {
            CPA_WAIT0();
        }
        __syncthreads();

#pragma unroll
        for (int ks = 0; ks < 4; ks++) {
            uint32_t av[2][4];
#pragma unroll
            for (int tm = 0; tm < 2; tm++) {
                int rA = wm * 32 + tm * 16 + (lane & 15);
                int ch = 2 * ks + (lane >> 4);
                ldsm4(av[tm], sb + st + sw128(rA, ch));
            }
#pragma unroll
            for (int g = 0; g < 2; g++) {
                int rB  = wn * 32 + g * 16 + ((lane >> 4) & 1) * 8 + (lane & 7);
                int chb = 2 * ks + ((lane >> 3) & 1);
                uint32_t bd = sb + st + OBH + sw128(rB, chb);
                uint32_t bh[4], bl[4];
                ldsm4(bh, bd);
                ldsm4(bl, bd + (OBL - OBH));
#pragma unroll
                for (int tm = 0; tm < 2; tm++) {
                    mma_f16(acc[tm][2*g],   av[tm], bh);        // A*Wh
                    mma_f16(acc[tm][2*g],   av[tm], bl);        // A*Wl
                    mma_f16(acc[tm][2*g+1], av[tm], bh + 2);
                    mma_f16(acc[tm][2*g+1], av[tm], bl + 2);
                }
            }
        }
        __syncthreads();
    }

    // ---- epilogue ----
    const int row_in = lane >> 2;
    const int col_in = 2 * (lane & 3);
#pragma unroll
    for (int tm = 0; tm < 2; tm++) {
        const int gr0 = row0 + wm * 32 + tm * 16 + row_in;
#pragma unroll
        for (int j = 0; j < 4; j++) {
            const int gcol = col0 + wn * 32 + j * 8 + col_in;
            const float bx = bias[gcol];
            const float by = bias[gcol + 1];
            if (Ch) {
                if (gr0 < M)
                    *(__half2*)&Ch[(size_t)gr0 * N + gcol] =
                        __floats2half2_rn(acc[tm][j][0] + bx, acc[tm][j][1] + by);
                if (gr0 + 8 < M)
                    *(__half2*)&Ch[(size_t)(gr0 + 8) * N + gcol] =
                        __floats2half2_rn(acc[tm][j][2] + bx, acc[tm][j][3] + by);
            } else {
                if (gr0 < M)
                    *(float2*)&Cf[(size_t)gr0 * N + gcol] =
                        make_float2(acc[tm][j][0] + bx, acc[tm][j][1] + by);
                if (gr0 + 8 < M)
                    *(float2*)&Cf[(size_t)(gr0 + 8) * N + gcol] =
                        make_float2(acc[tm][j][2] + bx, acc[tm][j][3] + by);
            }
        }
    }
#undef LOAD_STAGE
}

// ---------------------------------------------------------------------------
// Sampler: R14 verbatim (LDG.128, 4 lanes/corner, butterfly reduce)
// ---------------------------------------------------------------------------
#define QPB 2

__global__ __launch_bounds__(256) void deform_sample(
    const float* __restrict__ ref_points, float* __restrict__ out)
{
    __shared__ float4 s_w[QPB * COMBOS];
    __shared__ int4   s_i[QPB * COMBOS];

    const int t = threadIdx.x;

    // ---------------- Phase 1 ----------------
    {
        const int q    = t >> 7;
        const int c    = t & 127;
        const int head = c >> 4;
        const int i16  = c & 15;
        const int lv   = i16 >> 2;
        const int bn   = blockIdx.x * QPB + q;
        const int b    = bn / NQ;

        float lg = g_qc[(size_t)bn * NQC + 256 + c];
        float mx = lg;
#pragma unroll
        for (int s = 8; s >= 1; s >>= 1)
            mx = fmaxf(mx, __shfl_xor_sync(0xffffffffu, mx, s));
        float e = __expf(lg - mx);
        float ssum = e;
#pragma unroll
        for (int s = 8; s >= 1; s >>= 1)
            ssum += __shfl_xor_sync(0xffffffffu, ssum, s);
        const float aw = e / ssum;

        const float2 od = *(const float2*)&g_qc[(size_t)bn * NQC + 2 * c];
        const float rx = ref_points[bn * 2 + 0];
        const float ry = ref_points[bn * 2 + 1];

        const int   S  = c_shape[lv];
        const float fS = (float)S;
        const float x = (rx + od.x / fS) * fS - 0.5f;
        const float y = (ry + od.y / fS) * fS - 0.5f;
        const float x0f = floorf(x), y0f = floorf(y);
        const float lx = x - x0f, ly = y - y0f;
        const int x0 = (int)x0f, y0 = (int)y0f;
        const int x1 = x0 + 1,   y1 = y0 + 1;

        const bool vx0 = ((unsigned)x0 < (unsigned)S);
        const bool vx1 = ((unsigned)x1 < (unsigned)S);
        const bool vy0 = ((unsigned)y0 < (unsigned)S);
        const bool vy1 = ((unsigned)y1 < (unsigned)S);

        const int xc0 = min(max(x0, 0), S - 1);
        const int xc1 = min(max(x1, 0), S - 1);
        const int yc0 = min(max(y0, 0), S - 1);
        const int yc1 = min(max(y1, 0), S - 1);

        float4 wv;
        wv.x = (vx0 && vy0) ? (1.f - lx) * (1.f - ly) * aw : 0.f;
        wv.y = (vx1 && vy0) ? lx * (1.f - ly) * aw : 0.f;
        wv.z = (vx0 && vy1) ? (1.f - lx) * ly * aw : 0.f;
        wv.w = (vx1 && vy1) ? lx * ly * aw : 0.f;

        const int base = b * MTOT + c_start[lv];
        const int hoff = head * HEAD_DIM;
        int4 iv;
        iv.x = (base + yc0 * S + xc0) * EMBED + hoff;
        iv.y = (base + yc0 * S + xc1) * EMBED + hoff;
        iv.z = (base + yc1 * S + xc0) * EMBED + hoff;
        iv.w = (base + yc1 * S + xc1) * EMBED + hoff;

        s_w[t] = wv;
        s_i[t] = iv;
    }
    __syncthreads();

    // ---------------- Phase 2 ----------------
    const int head  = t >> 5;
    const int lane  = t & 31;
    const int cslot = lane >> 2;
    const int sub   = cslot >> 2;
    const int corner= cslot & 3;
    const int choff = (lane & 3) * 8;

    const int*   si  = (const int*)s_i;
    const float* swf = (const float*)s_w;

#pragma unroll
    for (int q = 0; q < QPB; q++) {
        const int bn   = blockIdx.x * QPB + q;
        const int slot = q * COMBOS + head * (LEVELS * POINTS);

        float acc[8];
#pragma unroll
        for (int j = 0; j < 8; j++) acc[j] = 0.f;

#pragma unroll
        for (int i = 0; i < 8; i++) {
            const int e   = (slot + 2 * i + sub) * 4 + corner;
            const int idx = si[e];
            const float w = swf[e];
            const uint4 d = __ldg((const uint4*)&g_vh[idx + choff]);
            const __half2* h2 = (const __half2*)&d;
#pragma unroll
            for (int j = 0; j < 4; j++) {
                float2 f = __half22float2(h2[j]);
                acc[2*j]   = fmaf(w, f.x, acc[2*j]);
                acc[2*j+1] = fmaf(w, f.y, acc[2*j+1]);
            }
        }

#pragma unroll
        for (int s = 4; s <= 16; s <<= 1)
#pragma unroll
            for (int j = 0; j < 8; j++)
                acc[j] += __shfl_xor_sync(0xffffffffu, acc[j], s);

        if (lane < 4) {
            float* op = out + (size_t)bn * EMBED + head * HEAD_DIM + choff;
            *(float4*)op       = make_float4(acc[0], acc[1], acc[2], acc[3]);
            *(float4*)(op + 4) = make_float4(acc[4], acc[5], acc[6], acc[7]);
        }
    }
}

// ---------------------------------------------------------------------------
// Launch: 3 kernels total
// ---------------------------------------------------------------------------
extern "C" void kernel_launch(void* const* d_in, const int* in_sizes, int n_in,
                              void* d_out, int out_size)
{
    const float* query  = (const float*)d_in[0];
    const float* value  = (const float*)d_in[2];
    const float* refpts = (const float*)d_in[3];
    const float* W_off  = (const float*)d_in[6];
    const float* b_off  = (const float*)d_in[7];
    const float* W_attn = (const float*)d_in[8];
    const float* b_attn = (const float*)d_in[9];
    const float* W_v    = (const float*)d_in[10];
    const float* b_v    = (const float*)d_in[11];
    float* out = (float*)d_out;

    cudaFuncSetAttribute(gemm_fused, cudaFuncAttributeMaxDynamicSharedMemorySize, SM_TOTAL);

    prep_all<<<(PREP_TOT + 255) / 256, 256>>>(value, query, W_v, W_off, W_attn,
                                              b_off, b_attn);

    gemm_fused<<<GRID_V + GRID_Q, 512, SM_TOTAL>>>(b_v);

    deform_sample<<<(BATCH * NQ) / QPB, 256>>>(refpts, out);
}